// round 1
// baseline (speedup 1.0000x reference)
#include <cuda_runtime.h>
#include <cstdint>
#include <cstddef>

#define NN   100000
#define EE   1000000
#define ETT  200000
#define FFI  64
#define DDI  32
#define HH   66
#define LLY  2
#define BN_EPS 1e-5f

// ---------------- scratch (static device globals; no allocation) ----------------
__device__ float g_h   [(size_t)NN  * HH];   // node features
__device__ float g_ea  [(size_t)EE  * HH];   // embedded edge attrs
__device__ float g_tea [(size_t)ETT * HH];   // embedded target-edge attrs (updated per layer)
__device__ float g_aggr[(size_t)NN  * HH];   // h + segment_sum(msg)
__device__ float g_t   [(size_t)NN  * HH];   // conv hidden
__device__ float g_z   [(size_t)NN  * HH];   // conv out (pre-BN)
__device__ float g_ehid[(size_t)ETT * HH];   // edge-update hidden
__device__ float g_o1  [(size_t)ETT * 50];   // final MLP hidden 1
__device__ float g_sum[HH];                  // BN partial sums (zero-init, re-zeroed each use)
__device__ float g_sumsq[HH];
__device__ float g_mean[HH];
__device__ float g_invstd[HH];

static inline int cdiv(int a, int b) { return (a + b - 1) / b; }

// ---------------- generic tall-skinny row GEMM: out = f(A@W + b) ----------------
// MODE 0: plain; MODE 1: relu; MODE 2: out = out + 0.5*(A@W+b)  (tea update, in-place on out)
template <int K, int HOUT, int MODE>
__global__ void __launch_bounds__(128)
rowgemm_kernel(const float* __restrict__ A, const float* __restrict__ W,
               const float* __restrict__ bias, float* __restrict__ out, int M)
{
    constexpr int HP = (HOUT + 3) & ~3;
    __shared__ float sW[K * HP];
    __shared__ float sb[HOUT];
    for (int i = threadIdx.x; i < K * HOUT; i += blockDim.x) {
        int k = i / HOUT, j = i % HOUT;
        sW[k * HP + j] = W[i];
    }
    for (int i = threadIdx.x; i < HOUT; i += blockDim.x) sb[i] = bias[i];
    __syncthreads();

    int r = blockIdx.x * blockDim.x + threadIdx.x;
    if (r >= M) return;

    float acc[HOUT];
#pragma unroll
    for (int j = 0; j < HOUT; j++) acc[j] = sb[j];

    const float* a = A + (size_t)r * K;
#pragma unroll 4
    for (int k = 0; k < K; k++) {
        float av = __ldg(&a[k]);
        const float* wr = &sW[k * HP];
#pragma unroll
        for (int j = 0; j < HOUT; j++) acc[j] = fmaf(av, wr[j], acc[j]);
    }

    float* o = out + (size_t)r * HOUT;
#pragma unroll
    for (int j = 0; j < HOUT; j++) {
        float v = acc[j];
        if (MODE == 1) v = fmaxf(v, 0.0f);
        if (MODE == 2) v = o[j] + 0.5f * v;
        o[j] = v;
    }
}

// ---------------- float4 copy (aggr <- h) ----------------
__global__ void copy4_kernel(const float4* __restrict__ src, float4* __restrict__ dst, int n4)
{
    for (int i = blockIdx.x * blockDim.x + threadIdx.x; i < n4; i += gridDim.x * blockDim.x)
        dst[i] = src[i];
}

// ---------------- scatter: aggr[dst] += relu(h[src] + ea), warp per edge ----------------
__global__ void scatter_kernel(const float* __restrict__ h, const float* __restrict__ ea,
                               const int* __restrict__ src, const int* __restrict__ dst,
                               float* __restrict__ aggr, int E)
{
    int warp = (blockIdx.x * blockDim.x + threadIdx.x) >> 5;
    int lane = threadIdx.x & 31;
    if (warp >= E) return;
    int s = src[warp];
    int d = dst[warp];
    const float* hs = h  + (size_t)s    * HH;
    const float* ee = ea + (size_t)warp * HH;
    float*       ag = aggr + (size_t)d  * HH;
    for (int c = lane; c < HH; c += 32) {
        float v = hs[c] + ee[c];
        v = fmaxf(v, 0.0f);
        atomicAdd(&ag[c], v);
    }
}

// ---------------- BN stats: per-channel sum / sumsq of g_z ----------------
__global__ void bnstats_kernel(const float* __restrict__ z, int M)
{
    __shared__ float ssum[8][HH + 2];
    __shared__ float ssq [8][HH + 2];
    int c  = threadIdx.x;   // 0..65
    int ty = threadIdx.y;   // 0..7
    float s = 0.f, q = 0.f;
    for (int r = blockIdx.x * 8 + ty; r < M; r += gridDim.x * 8) {
        float v = z[(size_t)r * HH + c];
        s += v; q += v * v;
    }
    ssum[ty][c] = s; ssq[ty][c] = q;
    __syncthreads();
    for (int off = 4; off >= 1; off >>= 1) {
        if (ty < off) { ssum[ty][c] += ssum[ty + off][c]; ssq[ty][c] += ssq[ty + off][c]; }
        __syncthreads();
    }
    if (ty == 0) {
        atomicAdd(&g_sum[c],   ssum[0][c]);
        atomicAdd(&g_sumsq[c], ssq[0][c]);
    }
}

__global__ void bnfinal_kernel(int n)
{
    int c = threadIdx.x;
    if (c < HH) {
        float m = g_sum[c] / (float)n;
        float v = g_sumsq[c] / (float)n - m * m;
        g_mean[c] = m;
        g_invstd[c] = rsqrtf(v + BN_EPS);
        g_sum[c] = 0.0f;     // leave zeroed for the next use / next launch
        g_sumsq[c] = 0.0f;
    }
}

// ---------------- h <- (h + relu(BN(z))) / 2 ----------------
__global__ void hup_kernel(const float* __restrict__ gamma, const float* __restrict__ beta, int M)
{
    int c = threadIdx.x;
    int r = blockIdx.x * blockDim.y + threadIdx.y;
    if (r >= M) return;
    size_t i = (size_t)r * HH + c;
    float bn = (g_z[i] - g_mean[c]) * g_invstd[c] * gamma[c] + beta[c];
    g_h[i] = 0.5f * (g_h[i] + fmaxf(bn, 0.0f));
}

// ---------------- edge-update GEMM1 (gathered cat[h[ts], h[td], tea] @ W1, relu) ----------------
__global__ void __launch_bounds__(128)
eu1_kernel(const float* __restrict__ h, const float* __restrict__ tea,
           const int* __restrict__ tsrc, const int* __restrict__ tdst,
           const float* __restrict__ W, const float* __restrict__ bias,
           float* __restrict__ out, int M)
{
    extern __shared__ float dsm[];
    float* sW = dsm;                  // [198][68]
    float* sb = dsm + 198 * 68;       // [66]
    for (int i = threadIdx.x; i < 198 * HH; i += blockDim.x) {
        int k = i / HH, j = i % HH;
        sW[k * 68 + j] = W[i];
    }
    for (int i = threadIdx.x; i < HH; i += blockDim.x) sb[i] = bias[i];
    __syncthreads();

    int r = blockIdx.x * blockDim.x + threadIdx.x;
    if (r >= M) return;

    float acc[HH];
#pragma unroll
    for (int j = 0; j < HH; j++) acc[j] = sb[j];

    int s = tsrc[r], d = tdst[r];
    const float* a0 = h   + (size_t)s * HH;
    const float* a1 = h   + (size_t)d * HH;
    const float* a2 = tea + (size_t)r * HH;

#pragma unroll 2
    for (int k = 0; k < HH; k++) {
        float av = __ldg(&a0[k]);
        const float* wr = &sW[k * 68];
#pragma unroll
        for (int j = 0; j < HH; j++) acc[j] = fmaf(av, wr[j], acc[j]);
    }
#pragma unroll 2
    for (int k = 0; k < HH; k++) {
        float av = __ldg(&a1[k]);
        const float* wr = &sW[(HH + k) * 68];
#pragma unroll
        for (int j = 0; j < HH; j++) acc[j] = fmaf(av, wr[j], acc[j]);
    }
#pragma unroll 2
    for (int k = 0; k < HH; k++) {
        float av = __ldg(&a2[k]);
        const float* wr = &sW[(2 * HH + k) * 68];
#pragma unroll
        for (int j = 0; j < HH; j++) acc[j] = fmaf(av, wr[j], acc[j]);
    }

    float* o = out + (size_t)r * HH;
#pragma unroll
    for (int j = 0; j < HH; j++) o[j] = fmaxf(acc[j], 0.0f);
}

// ---------------- final MLP layer 1 (gathered [relu(h[ts]), relu(h[td]), tea] @ W1, relu) ----------------
__global__ void __launch_bounds__(128)
f1_kernel(const float* __restrict__ h, const float* __restrict__ tea,
          const int* __restrict__ tsrc, const int* __restrict__ tdst,
          const float* __restrict__ W, const float* __restrict__ bias,
          float* __restrict__ out, int M)
{
    __shared__ float sW[198 * 52];    // [198][52] pad
    __shared__ float sb[50];
    for (int i = threadIdx.x; i < 198 * 50; i += blockDim.x) {
        int k = i / 50, j = i % 50;
        sW[k * 52 + j] = W[i];
    }
    for (int i = threadIdx.x; i < 50; i += blockDim.x) sb[i] = bias[i];
    __syncthreads();

    int r = blockIdx.x * blockDim.x + threadIdx.x;
    if (r >= M) return;

    float acc[50];
#pragma unroll
    for (int j = 0; j < 50; j++) acc[j] = sb[j];

    int s = tsrc[r], d = tdst[r];
    const float* a0 = h   + (size_t)s * HH;
    const float* a1 = h   + (size_t)d * HH;
    const float* a2 = tea + (size_t)r * HH;

#pragma unroll 2
    for (int k = 0; k < HH; k++) {
        float av = fmaxf(__ldg(&a0[k]), 0.0f);
        const float* wr = &sW[k * 52];
#pragma unroll
        for (int j = 0; j < 50; j++) acc[j] = fmaf(av, wr[j], acc[j]);
    }
#pragma unroll 2
    for (int k = 0; k < HH; k++) {
        float av = fmaxf(__ldg(&a1[k]), 0.0f);
        const float* wr = &sW[(HH + k) * 52];
#pragma unroll
        for (int j = 0; j < 50; j++) acc[j] = fmaf(av, wr[j], acc[j]);
    }
#pragma unroll 2
    for (int k = 0; k < HH; k++) {
        float av = __ldg(&a2[k]);
        const float* wr = &sW[(2 * HH + k) * 52];
#pragma unroll
        for (int j = 0; j < 50; j++) acc[j] = fmaf(av, wr[j], acc[j]);
    }

    float* o = out + (size_t)r * 50;
#pragma unroll
    for (int j = 0; j < 50; j++) o[j] = fmaxf(acc[j], 0.0f);
}

// ---------------- final MLP layers 2+3 fused: out = relu(o1@W2+b2)@W3+b3 ----------------
__global__ void __launch_bounds__(128)
f23_kernel(const float* __restrict__ o1,
           const float* __restrict__ W2, const float* __restrict__ b2,
           const float* __restrict__ W3, const float* __restrict__ b3,
           float* __restrict__ out, int M)
{
    __shared__ float sW2[50 * 28];   // [50][28] pad (25 cols)
    __shared__ float sW3[25 * 4];    // [25][4] pad (2 cols)
    __shared__ float sb2[25];
    __shared__ float sb3[2];
    for (int i = threadIdx.x; i < 50 * 25; i += blockDim.x) {
        int k = i / 25, j = i % 25;
        sW2[k * 28 + j] = W2[i];
    }
    for (int i = threadIdx.x; i < 25 * 2; i += blockDim.x) {
        int k = i / 2, j = i % 2;
        sW3[k * 4 + j] = W3[i];
    }
    if (threadIdx.x < 25) sb2[threadIdx.x] = b2[threadIdx.x];
    if (threadIdx.x < 2)  sb3[threadIdx.x] = b3[threadIdx.x];
    __syncthreads();

    int r = blockIdx.x * blockDim.x + threadIdx.x;
    if (r >= M) return;

    float acc[25];
#pragma unroll
    for (int j = 0; j < 25; j++) acc[j] = sb2[j];
    const float* a = o1 + (size_t)r * 50;
#pragma unroll 2
    for (int k = 0; k < 50; k++) {
        float av = __ldg(&a[k]);
        const float* wr = &sW2[k * 28];
#pragma unroll
        for (int j = 0; j < 25; j++) acc[j] = fmaf(av, wr[j], acc[j]);
    }
    float o0 = sb3[0], o1v = sb3[1];
#pragma unroll
    for (int k = 0; k < 25; k++) {
        float av = fmaxf(acc[k], 0.0f);
        o0 = fmaf(av, sW3[k * 4 + 0], o0);
        o1v = fmaf(av, sW3[k * 4 + 1], o1v);
    }
    out[(size_t)r * 2 + 0] = o0;
    out[(size_t)r * 2 + 1] = o1v;
}

// =======================================================================================
extern "C" void kernel_launch(void* const* d_in, const int* in_sizes, int n_in,
                              void* d_out, int out_size)
{
    // ---- resolve input ordering: dict order (setup_inputs) vs signature order ----
    const float *x, *edge_attr, *tea_in, *node_w, *node_b, *edge_w, *edge_b;
    const float *conv_w1, *conv_b1, *conv_w2, *conv_b2, *bn_gamma, *bn_beta;
    const float *emlp_w1, *emlp_b1, *emlp_w2, *emlp_b2;
    const float *mlp_w1, *mlp_b1, *mlp_w2, *mlp_b2, *mlp_w3, *mlp_b3;
    const int *edge_index, *eli;

    if (in_sizes[1] == 2 * EE) {
        // dict order: x, edge_index, edge_attr, edge_label_index, target_edge_attr, ...
        x          = (const float*)d_in[0];
        edge_index = (const int*)  d_in[1];
        edge_attr  = (const float*)d_in[2];
        eli        = (const int*)  d_in[3];
        tea_in     = (const float*)d_in[4];
        node_w = (const float*)d_in[5];  node_b = (const float*)d_in[6];
        edge_w = (const float*)d_in[7];  edge_b = (const float*)d_in[8];
        conv_w1 = (const float*)d_in[9];  conv_b1 = (const float*)d_in[10];
        conv_w2 = (const float*)d_in[11]; conv_b2 = (const float*)d_in[12];
        bn_gamma = (const float*)d_in[13]; bn_beta = (const float*)d_in[14];
        emlp_w1 = (const float*)d_in[15]; emlp_b1 = (const float*)d_in[16];
        emlp_w2 = (const float*)d_in[17]; emlp_b2 = (const float*)d_in[18];
        mlp_w1 = (const float*)d_in[19]; mlp_b1 = (const float*)d_in[20];
        mlp_w2 = (const float*)d_in[21]; mlp_b2 = (const float*)d_in[22];
        mlp_w3 = (const float*)d_in[23]; mlp_b3 = (const float*)d_in[24];
    } else {
        // signature order: x, edge_attr, target_edge_attr, ..., edge_index, edge_label_index
        x         = (const float*)d_in[0];
        edge_attr = (const float*)d_in[1];
        tea_in    = (const float*)d_in[2];
        node_w = (const float*)d_in[3];  node_b = (const float*)d_in[4];
        edge_w = (const float*)d_in[5];  edge_b = (const float*)d_in[6];
        conv_w1 = (const float*)d_in[7];  conv_b1 = (const float*)d_in[8];
        conv_w2 = (const float*)d_in[9];  conv_b2 = (const float*)d_in[10];
        bn_gamma = (const float*)d_in[11]; bn_beta = (const float*)d_in[12];
        emlp_w1 = (const float*)d_in[13]; emlp_b1 = (const float*)d_in[14];
        emlp_w2 = (const float*)d_in[15]; emlp_b2 = (const float*)d_in[16];
        mlp_w1 = (const float*)d_in[17]; mlp_b1 = (const float*)d_in[18];
        mlp_w2 = (const float*)d_in[19]; mlp_b2 = (const float*)d_in[20];
        mlp_w3 = (const float*)d_in[21]; mlp_b3 = (const float*)d_in[22];
        edge_index = (const int*)d_in[23];
        eli        = (const int*)d_in[24];
    }

    const int* e_src = edge_index;
    const int* e_dst = edge_index + EE;
    const int* tsrc  = eli;
    const int* tdst  = eli + ETT;

    // ---- scratch addresses ----
    float *p_h, *p_ea, *p_tea, *p_aggr, *p_t, *p_z, *p_ehid, *p_o1;
    cudaGetSymbolAddress((void**)&p_h,    g_h);
    cudaGetSymbolAddress((void**)&p_ea,   g_ea);
    cudaGetSymbolAddress((void**)&p_tea,  g_tea);
    cudaGetSymbolAddress((void**)&p_aggr, g_aggr);
    cudaGetSymbolAddress((void**)&p_t,    g_t);
    cudaGetSymbolAddress((void**)&p_z,    g_z);
    cudaGetSymbolAddress((void**)&p_ehid, g_ehid);
    cudaGetSymbolAddress((void**)&p_o1,   g_o1);

    const int eu1_smem = (198 * 68 + HH) * 4;
    cudaFuncSetAttribute(eu1_kernel, cudaFuncAttributeMaxDynamicSharedMemorySize, eu1_smem);

    // ---- embeddings ----
    rowgemm_kernel<FFI, HH, 0><<<cdiv(NN, 128), 128>>>(x, node_w, node_b, p_h, NN);
    rowgemm_kernel<DDI, HH, 0><<<cdiv(EE, 128), 128>>>(edge_attr, edge_w, edge_b, p_ea, EE);
    rowgemm_kernel<DDI, HH, 0><<<cdiv(ETT, 128), 128>>>(tea_in, edge_w, edge_b, p_tea, ETT);

    // ---- layers ----
    for (int l = 0; l < LLY; l++) {
        // aggr = h
        copy4_kernel<<<2048, 256>>>((const float4*)p_h, (float4*)p_aggr, NN * HH / 4);
        // aggr[dst] += relu(h[src] + ea)
        scatter_kernel<<<cdiv(EE * 32, 256), 256>>>(p_h, p_ea, e_src, e_dst, p_aggr, EE);
        // conv MLP
        rowgemm_kernel<HH, HH, 1><<<cdiv(NN, 128), 128>>>(p_aggr, conv_w1 + l * HH * HH,
                                                          conv_b1 + l * HH, p_t, NN);
        rowgemm_kernel<HH, HH, 0><<<cdiv(NN, 128), 128>>>(p_t, conv_w2 + l * HH * HH,
                                                          conv_b2 + l * HH, p_z, NN);
        // BatchNorm (batch stats)
        {
            dim3 bs(HH, 8);
            bnstats_kernel<<<264, bs>>>(p_z, NN);
        }
        bnfinal_kernel<<<1, HH>>>(NN);
        {
            dim3 bs(HH, 4);
            hup_kernel<<<cdiv(NN, 4), bs>>>(bn_gamma + l * HH, bn_beta + l * HH, NN);
        }
        // edge update on target edges
        eu1_kernel<<<cdiv(ETT, 128), 128, eu1_smem>>>(p_h, p_tea, tsrc, tdst,
                                                      emlp_w1 + l * 3 * HH * HH,
                                                      emlp_b1 + l * HH, p_ehid, ETT);
        rowgemm_kernel<HH, HH, 2><<<cdiv(ETT, 128), 128>>>(p_ehid, emlp_w2 + l * HH * HH,
                                                           emlp_b2 + l * HH, p_tea, ETT);
    }

    // ---- final classifier ----
    f1_kernel<<<cdiv(ETT, 128), 128>>>(p_h, p_tea, tsrc, tdst, mlp_w1, mlp_b1, p_o1, ETT);
    f23_kernel<<<cdiv(ETT, 128), 128>>>(p_o1, mlp_w2, mlp_b2, mlp_w3, mlp_b3,
                                        (float*)d_out, ETT);
}

// round 2
// speedup vs baseline: 2.2530x; 2.2530x over previous
#include <cuda_runtime.h>
#include <cstdint>
#include <cstddef>

#define NN   100000
#define EE   1000000
#define ETT  200000
#define FFI  64
#define DDI  32
#define HH   66
#define HS   68          // padded row stride for H-wide scratch (16B aligned)
#define LLY  2
#define BN_EPS 1e-5f

static inline int cdiv(int a, int b) { return (a + b - 1) / b; }

// ---------------- scratch (static device globals; zero-initialized, no allocation) ----
// Padding columns [66,67] of every H-wide array are NEVER written -> stay 0 forever.
__device__ float g_h   [(size_t)NN  * HS];
__device__ float g_ea  [(size_t)EE  * HS];   // embedded edge attrs, dst-sorted order
__device__ float g_tea [(size_t)ETT * HS];
__device__ float g_aggr[(size_t)NN  * HS];
__device__ float g_t   [(size_t)NN  * HS];
__device__ float g_z   [(size_t)NN  * HS];
__device__ float g_ehid[(size_t)ETT * HS];
__device__ float g_o1  [(size_t)ETT * 52];
__device__ float g_sum[HH];
__device__ float g_sumsq[HH];
__device__ float g_mean[HH];
__device__ float g_invstd[HH];
// CSR scratch
__device__ int g_cnt[NN];
__device__ int g_rowstart[NN + 1];
__device__ int g_cursor[NN];
__device__ int g_bsum[128];
__device__ int g_boff[128];
__device__ int g_perm[EE];     // sorted pos -> original edge id
__device__ int g_srcs[EE];     // sorted pos -> src node

// ================= CSR build =================
__global__ void zero_cnt_kernel()
{
    int i = blockIdx.x * blockDim.x + threadIdx.x;
    if (i < NN) g_cnt[i] = 0;
}

__global__ void hist_kernel(const int* __restrict__ dst)
{
    int e = blockIdx.x * blockDim.x + threadIdx.x;
    if (e < EE) atomicAdd(&g_cnt[dst[e]], 1);
}

__global__ void scan1_kernel()
{
    __shared__ int sh[1024];
    int i = blockIdx.x * 1024 + threadIdx.x;
    int v = (i < NN) ? g_cnt[i] : 0;
    sh[threadIdx.x] = v;
    __syncthreads();
    for (int off = 1; off < 1024; off <<= 1) {
        int t = (threadIdx.x >= off) ? sh[threadIdx.x - off] : 0;
        __syncthreads();
        sh[threadIdx.x] += t;
        __syncthreads();
    }
    if (i < NN) g_rowstart[i] = sh[threadIdx.x] - v;   // block-exclusive
    if (threadIdx.x == 1023) g_bsum[blockIdx.x] = sh[1023];
}

__global__ void scan2_kernel(int nb)
{
    __shared__ int sh[128];
    int t = threadIdx.x;
    int v = (t < nb) ? g_bsum[t] : 0;
    sh[t] = v;
    __syncthreads();
    for (int off = 1; off < 128; off <<= 1) {
        int u = (t >= off) ? sh[t - off] : 0;
        __syncthreads();
        sh[t] += u;
        __syncthreads();
    }
    g_boff[t] = sh[t] - v;   // exclusive
}

__global__ void scan3_kernel()
{
    int i = blockIdx.x * blockDim.x + threadIdx.x;
    if (i < NN) {
        int rs = g_rowstart[i] + g_boff[i >> 10];
        g_rowstart[i] = rs;
        g_cursor[i] = rs;
    }
    if (i == 0) g_rowstart[NN] = EE;
}

__global__ void place_kernel(const int* __restrict__ src, const int* __restrict__ dst)
{
    int e = blockIdx.x * blockDim.x + threadIdx.x;
    if (e >= EE) return;
    int d = dst[e];
    int pos = atomicAdd(&g_cursor[d], 1);
    g_perm[pos] = e;
    g_srcs[pos] = src[e];
}

// ================= generic tall-skinny row GEMM =================
// out[r,:] = f(A[ra,:] @ W + b), A row stride = KP, out row stride = HP
// MODE 0: plain; MODE 1: relu; MODE 2: out += 0.5*(A@W+b) in-place
template <int K, int HOUT, int MODE, bool GATHER>
__global__ void __launch_bounds__(128)
rowgemm(const float* __restrict__ A, const float* __restrict__ W,
        const float* __restrict__ bias, float* __restrict__ out,
        const int* __restrict__ perm, int M)
{
    constexpr int KP = (K + 3) & ~3;
    constexpr int HP = (HOUT + 3) & ~3;
    __shared__ float sW[KP * HP];
    __shared__ float sb[HP];
    for (int i = threadIdx.x; i < KP * HP; i += blockDim.x) {
        int k = i / HP, j = i % HP;
        sW[i] = (k < K && j < HOUT) ? W[k * HOUT + j] : 0.0f;
    }
    for (int i = threadIdx.x; i < HP; i += blockDim.x)
        sb[i] = (i < HOUT) ? bias[i] : 0.0f;
    __syncthreads();

    int r = blockIdx.x * blockDim.x + threadIdx.x;
    if (r >= M) return;
    int ra = GATHER ? perm[r] : r;

    float acc[HP];
#pragma unroll
    for (int j = 0; j < HP; j++) acc[j] = sb[j];

    const float4* a4 = reinterpret_cast<const float4*>(A + (size_t)ra * KP);
#pragma unroll 2
    for (int kk = 0; kk < KP / 4; kk++) {
        float4 av = __ldg(&a4[kk]);
#pragma unroll
        for (int s = 0; s < 4; s++) {
            float a = (s == 0) ? av.x : (s == 1) ? av.y : (s == 2) ? av.z : av.w;
            const float4* w4 = reinterpret_cast<const float4*>(&sW[(kk * 4 + s) * HP]);
#pragma unroll
            for (int j = 0; j < HP / 4; j++) {
                float4 w = w4[j];
                acc[4 * j + 0] = fmaf(a, w.x, acc[4 * j + 0]);
                acc[4 * j + 1] = fmaf(a, w.y, acc[4 * j + 1]);
                acc[4 * j + 2] = fmaf(a, w.z, acc[4 * j + 2]);
                acc[4 * j + 3] = fmaf(a, w.w, acc[4 * j + 3]);
            }
        }
    }

    float4* o4 = reinterpret_cast<float4*>(out + (size_t)r * HP);
#pragma unroll
    for (int j = 0; j < HP / 4; j++) {
        float4 v;
        v.x = acc[4 * j + 0]; v.y = acc[4 * j + 1];
        v.z = acc[4 * j + 2]; v.w = acc[4 * j + 3];
        if (MODE == 1) {
            v.x = fmaxf(v.x, 0.f); v.y = fmaxf(v.y, 0.f);
            v.z = fmaxf(v.z, 0.f); v.w = fmaxf(v.w, 0.f);
        }
        if (MODE == 2) {
            float4 ov = o4[j];
            v.x = ov.x + 0.5f * v.x; v.y = ov.y + 0.5f * v.y;
            v.z = ov.z + 0.5f * v.z; v.w = ov.w + 0.5f * v.w;
        }
        o4[j] = v;
    }
}

// ================= aggregation: aggr[n] = h[n] + sum_{e in seg(n)} relu(h[src]+ea) ====
__global__ void aggregate_kernel(const float* __restrict__ h, const float* __restrict__ ea,
                                 float* __restrict__ aggr)
{
    int warp = (blockIdx.x * blockDim.x + threadIdx.x) >> 5;
    int lane = threadIdx.x & 31;
    if (warp >= NN) return;
    int beg = g_rowstart[warp];
    int end = g_rowstart[warp + 1];
    bool has2 = lane < 2;
    int c2 = lane + 64;
    float a0 = 0.f, a1 = 0.f, a2 = 0.f;
    for (int p = beg; p < end; p++) {
        int s = g_srcs[p];
        const float* er = ea + (size_t)p * HS;
        const float* hr = h + (size_t)s * HS;
        a0 += fmaxf(hr[lane]      + er[lane],      0.f);
        a1 += fmaxf(hr[lane + 32] + er[lane + 32], 0.f);
        if (has2) a2 += fmaxf(hr[c2] + er[c2], 0.f);
    }
    const float* hd = h + (size_t)warp * HS;
    float* o = aggr + (size_t)warp * HS;
    o[lane]      = hd[lane]      + a0;
    o[lane + 32] = hd[lane + 32] + a1;
    if (has2) o[c2] = hd[c2] + a2;
}

// ================= BN stats / final / h update =================
__global__ void bnstats_kernel(const float* __restrict__ z, int M)
{
    __shared__ float ssum[8][HH + 2];
    __shared__ float ssq [8][HH + 2];
    int c  = threadIdx.x;
    int ty = threadIdx.y;
    float s = 0.f, q = 0.f;
    for (int r = blockIdx.x * 8 + ty; r < M; r += gridDim.x * 8) {
        float v = z[(size_t)r * HS + c];
        s += v; q += v * v;
    }
    ssum[ty][c] = s; ssq[ty][c] = q;
    __syncthreads();
    for (int off = 4; off >= 1; off >>= 1) {
        if (ty < off) { ssum[ty][c] += ssum[ty + off][c]; ssq[ty][c] += ssq[ty + off][c]; }
        __syncthreads();
    }
    if (ty == 0) {
        atomicAdd(&g_sum[c],   ssum[0][c]);
        atomicAdd(&g_sumsq[c], ssq[0][c]);
    }
}

__global__ void bnfinal_kernel(int n)
{
    int c = threadIdx.x;
    if (c < HH) {
        float m = g_sum[c] / (float)n;
        float v = g_sumsq[c] / (float)n - m * m;
        g_mean[c] = m;
        g_invstd[c] = rsqrtf(v + BN_EPS);
        g_sum[c] = 0.0f;
        g_sumsq[c] = 0.0f;
    }
}

__global__ void hup_kernel(const float* __restrict__ gamma, const float* __restrict__ beta, int M)
{
    int c = threadIdx.x;
    int r = blockIdx.x * blockDim.y + threadIdx.y;
    if (r >= M) return;
    size_t i = (size_t)r * HS + c;
    float bn = (g_z[i] - g_mean[c]) * g_invstd[c] * gamma[c] + beta[c];
    g_h[i] = 0.5f * (g_h[i] + fmaxf(bn, 0.0f));
}

// ================= edge-update GEMM1: relu(cat[h[ts],h[td],tea] @ W1 + b1) ===========
__global__ void __launch_bounds__(128)
eu1_kernel(const float* __restrict__ h, const float* __restrict__ tea,
           const int* __restrict__ tsrc, const int* __restrict__ tdst,
           const float* __restrict__ W, const float* __restrict__ bias,
           float* __restrict__ out, int M)
{
    extern __shared__ float dsm[];
    float* sW = dsm;             // [3*68][68]
    float* sb = dsm + 204 * 68;  // [68]
    for (int i = threadIdx.x; i < 204 * 68; i += blockDim.x) {
        int k = i / 68, j = i % 68;
        int seg = k / 68;  // 0 by construction of this index scheme below
        (void)seg;
        int segk = k % 68;
        int segi = k / 68;
        sW[i] = 0.0f;
        (void)segk; (void)segi;
    }
    __syncthreads();
    // proper fill: logical K rows 0..197 -> padded row seg*68 + kk
    for (int i = threadIdx.x; i < 198 * HH; i += blockDim.x) {
        int k = i / HH, j = i % HH;
        int seg = k / HH, kk = k % HH;
        sW[(seg * 68 + kk) * 68 + j] = W[k * HH + j];
    }
    for (int i = threadIdx.x; i < 68; i += blockDim.x)
        sb[i] = (i < HH) ? bias[i] : 0.0f;
    __syncthreads();

    int r = blockIdx.x * blockDim.x + threadIdx.x;
    if (r >= M) return;

    float acc[68];
#pragma unroll
    for (int j = 0; j < 68; j++) acc[j] = sb[j];

    int si = tsrc[r], di = tdst[r];
    const float* bases[3] = { h + (size_t)si * HS, h + (size_t)di * HS, tea + (size_t)r * HS };

#pragma unroll 1
    for (int seg = 0; seg < 3; seg++) {
        const float4* a4 = reinterpret_cast<const float4*>(bases[seg]);
#pragma unroll 2
        for (int kk = 0; kk < 17; kk++) {
            float4 av = __ldg(&a4[kk]);
#pragma unroll
            for (int s = 0; s < 4; s++) {
                float a = (s == 0) ? av.x : (s == 1) ? av.y : (s == 2) ? av.z : av.w;
                const float4* w4 = reinterpret_cast<const float4*>(&sW[(seg * 68 + kk * 4 + s) * 68]);
#pragma unroll
                for (int j = 0; j < 17; j++) {
                    float4 w = w4[j];
                    acc[4 * j + 0] = fmaf(a, w.x, acc[4 * j + 0]);
                    acc[4 * j + 1] = fmaf(a, w.y, acc[4 * j + 1]);
                    acc[4 * j + 2] = fmaf(a, w.z, acc[4 * j + 2]);
                    acc[4 * j + 3] = fmaf(a, w.w, acc[4 * j + 3]);
                }
            }
        }
    }

    float4* o4 = reinterpret_cast<float4*>(out + (size_t)r * HS);
#pragma unroll
    for (int j = 0; j < 17; j++) {
        float4 v;
        v.x = fmaxf(acc[4 * j + 0], 0.f); v.y = fmaxf(acc[4 * j + 1], 0.f);
        v.z = fmaxf(acc[4 * j + 2], 0.f); v.w = fmaxf(acc[4 * j + 3], 0.f);
        o4[j] = v;
    }
}

// ================= final MLP layer 1: relu([relu h[ts], relu h[td], tea] @ W1 + b1) ===
__global__ void __launch_bounds__(128)
f1_kernel(const float* __restrict__ h, const float* __restrict__ tea,
          const int* __restrict__ tsrc, const int* __restrict__ tdst,
          const float* __restrict__ W, const float* __restrict__ bias,
          float* __restrict__ out, int M)
{
    __shared__ float sW[204 * 52];
    __shared__ float sb[52];
    for (int i = threadIdx.x; i < 204 * 52; i += blockDim.x) sW[i] = 0.0f;
    __syncthreads();
    for (int i = threadIdx.x; i < 198 * 50; i += blockDim.x) {
        int k = i / 50, j = i % 50;
        int seg = k / HH, kk = k % HH;
        sW[(seg * 68 + kk) * 52 + j] = W[k * 50 + j];
    }
    for (int i = threadIdx.x; i < 52; i += blockDim.x)
        sb[i] = (i < 50) ? bias[i] : 0.0f;
    __syncthreads();

    int r = blockIdx.x * blockDim.x + threadIdx.x;
    if (r >= M) return;

    float acc[52];
#pragma unroll
    for (int j = 0; j < 52; j++) acc[j] = sb[j];

    int si = tsrc[r], di = tdst[r];
    const float* bases[3] = { h + (size_t)si * HS, h + (size_t)di * HS, tea + (size_t)r * HS };

#pragma unroll 1
    for (int seg = 0; seg < 3; seg++) {
        bool rl = (seg < 2);
        const float4* a4 = reinterpret_cast<const float4*>(bases[seg]);
#pragma unroll 2
        for (int kk = 0; kk < 17; kk++) {
            float4 av = __ldg(&a4[kk]);
            if (rl) {
                av.x = fmaxf(av.x, 0.f); av.y = fmaxf(av.y, 0.f);
                av.z = fmaxf(av.z, 0.f); av.w = fmaxf(av.w, 0.f);
            }
#pragma unroll
            for (int s = 0; s < 4; s++) {
                float a = (s == 0) ? av.x : (s == 1) ? av.y : (s == 2) ? av.z : av.w;
                const float4* w4 = reinterpret_cast<const float4*>(&sW[(seg * 68 + kk * 4 + s) * 52]);
#pragma unroll
                for (int j = 0; j < 13; j++) {
                    float4 w = w4[j];
                    acc[4 * j + 0] = fmaf(a, w.x, acc[4 * j + 0]);
                    acc[4 * j + 1] = fmaf(a, w.y, acc[4 * j + 1]);
                    acc[4 * j + 2] = fmaf(a, w.z, acc[4 * j + 2]);
                    acc[4 * j + 3] = fmaf(a, w.w, acc[4 * j + 3]);
                }
            }
        }
    }

    float4* o4 = reinterpret_cast<float4*>(out + (size_t)r * 52);
#pragma unroll
    for (int j = 0; j < 13; j++) {
        float4 v;
        v.x = fmaxf(acc[4 * j + 0], 0.f); v.y = fmaxf(acc[4 * j + 1], 0.f);
        v.z = fmaxf(acc[4 * j + 2], 0.f); v.w = fmaxf(acc[4 * j + 3], 0.f);
        o4[j] = v;
    }
}

// ================= final MLP layers 2+3 =================
__global__ void __launch_bounds__(128)
f23_kernel(const float* __restrict__ o1,
           const float* __restrict__ W2, const float* __restrict__ b2,
           const float* __restrict__ W3, const float* __restrict__ b3,
           float* __restrict__ out, int M)
{
    __shared__ float sW2[52 * 28];
    __shared__ float sW3[25 * 4];
    __shared__ float sb2[28];
    __shared__ float sb3[2];
    for (int i = threadIdx.x; i < 52 * 28; i += blockDim.x) {
        int k = i / 28, j = i % 28;
        sW2[i] = (k < 50 && j < 25) ? W2[k * 25 + j] : 0.0f;
    }
    for (int i = threadIdx.x; i < 25 * 4; i += blockDim.x) {
        int k = i / 4, j = i % 4;
        sW3[i] = (j < 2) ? W3[k * 2 + j] : 0.0f;
    }
    if (threadIdx.x < 28) sb2[threadIdx.x] = (threadIdx.x < 25) ? b2[threadIdx.x] : 0.0f;
    if (threadIdx.x < 2)  sb3[threadIdx.x] = b3[threadIdx.x];
    __syncthreads();

    int r = blockIdx.x * blockDim.x + threadIdx.x;
    if (r >= M) return;

    float acc[28];
#pragma unroll
    for (int j = 0; j < 28; j++) acc[j] = sb2[j];

    const float4* a4 = reinterpret_cast<const float4*>(o1 + (size_t)r * 52);
#pragma unroll 2
    for (int kk = 0; kk < 13; kk++) {
        float4 av = __ldg(&a4[kk]);
#pragma unroll
        for (int s = 0; s < 4; s++) {
            float a = (s == 0) ? av.x : (s == 1) ? av.y : (s == 2) ? av.z : av.w;
            const float4* w4 = reinterpret_cast<const float4*>(&sW2[(kk * 4 + s) * 28]);
#pragma unroll
            for (int j = 0; j < 7; j++) {
                float4 w = w4[j];
                acc[4 * j + 0] = fmaf(a, w.x, acc[4 * j + 0]);
                acc[4 * j + 1] = fmaf(a, w.y, acc[4 * j + 1]);
                acc[4 * j + 2] = fmaf(a, w.z, acc[4 * j + 2]);
                acc[4 * j + 3] = fmaf(a, w.w, acc[4 * j + 3]);
            }
        }
    }
    float o0 = sb3[0], o1v = sb3[1];
#pragma unroll
    for (int k = 0; k < 25; k++) {
        float a = fmaxf(acc[k], 0.f);
        o0  = fmaf(a, sW3[k * 4 + 0], o0);
        o1v = fmaf(a, sW3[k * 4 + 1], o1v);
    }
    out[(size_t)r * 2 + 0] = o0;
    out[(size_t)r * 2 + 1] = o1v;
}

// =======================================================================================
extern "C" void kernel_launch(void* const* d_in, const int* in_sizes, int n_in,
                              void* d_out, int out_size)
{
    const float *x, *edge_attr, *tea_in, *node_w, *node_b, *edge_w, *edge_b;
    const float *conv_w1, *conv_b1, *conv_w2, *conv_b2, *bn_gamma, *bn_beta;
    const float *emlp_w1, *emlp_b1, *emlp_w2, *emlp_b2;
    const float *mlp_w1, *mlp_b1, *mlp_w2, *mlp_b2, *mlp_w3, *mlp_b3;
    const int *edge_index, *eli;

    if (in_sizes[1] == 2 * EE) {
        x          = (const float*)d_in[0];
        edge_index = (const int*)  d_in[1];
        edge_attr  = (const float*)d_in[2];
        eli        = (const int*)  d_in[3];
        tea_in     = (const float*)d_in[4];
        node_w = (const float*)d_in[5];  node_b = (const float*)d_in[6];
        edge_w = (const float*)d_in[7];  edge_b = (const float*)d_in[8];
        conv_w1 = (const float*)d_in[9];  conv_b1 = (const float*)d_in[10];
        conv_w2 = (const float*)d_in[11]; conv_b2 = (const float*)d_in[12];
        bn_gamma = (const float*)d_in[13]; bn_beta = (const float*)d_in[14];
        emlp_w1 = (const float*)d_in[15]; emlp_b1 = (const float*)d_in[16];
        emlp_w2 = (const float*)d_in[17]; emlp_b2 = (const float*)d_in[18];
        mlp_w1 = (const float*)d_in[19]; mlp_b1 = (const float*)d_in[20];
        mlp_w2 = (const float*)d_in[21]; mlp_b2 = (const float*)d_in[22];
        mlp_w3 = (const float*)d_in[23]; mlp_b3 = (const float*)d_in[24];
    } else {
        x         = (const float*)d_in[0];
        edge_attr = (const float*)d_in[1];
        tea_in    = (const float*)d_in[2];
        node_w = (const float*)d_in[3];  node_b = (const float*)d_in[4];
        edge_w = (const float*)d_in[5];  edge_b = (const float*)d_in[6];
        conv_w1 = (const float*)d_in[7];  conv_b1 = (const float*)d_in[8];
        conv_w2 = (const float*)d_in[9];  conv_b2 = (const float*)d_in[10];
        bn_gamma = (const float*)d_in[11]; bn_beta = (const float*)d_in[12];
        emlp_w1 = (const float*)d_in[13]; emlp_b1 = (const float*)d_in[14];
        emlp_w2 = (const float*)d_in[15]; emlp_b2 = (const float*)d_in[16];
        mlp_w1 = (const float*)d_in[17]; mlp_b1 = (const float*)d_in[18];
        mlp_w2 = (const float*)d_in[19]; mlp_b2 = (const float*)d_in[20];
        mlp_w3 = (const float*)d_in[21]; mlp_b3 = (const float*)d_in[22];
        edge_index = (const int*)d_in[23];
        eli        = (const int*)d_in[24];
    }

    const int* e_src = edge_index;
    const int* e_dst = edge_index + EE;
    const int* tsrc  = eli;
    const int* tdst  = eli + ETT;

    float *p_h, *p_ea, *p_tea, *p_aggr, *p_t, *p_z, *p_ehid, *p_o1;
    int *p_perm;
    cudaGetSymbolAddress((void**)&p_h,    g_h);
    cudaGetSymbolAddress((void**)&p_ea,   g_ea);
    cudaGetSymbolAddress((void**)&p_tea,  g_tea);
    cudaGetSymbolAddress((void**)&p_aggr, g_aggr);
    cudaGetSymbolAddress((void**)&p_t,    g_t);
    cudaGetSymbolAddress((void**)&p_z,    g_z);
    cudaGetSymbolAddress((void**)&p_ehid, g_ehid);
    cudaGetSymbolAddress((void**)&p_o1,   g_o1);
    cudaGetSymbolAddress((void**)&p_perm, g_perm);

    const int eu1_smem = (204 * 68 + 68) * 4;
    cudaFuncSetAttribute(eu1_kernel, cudaFuncAttributeMaxDynamicSharedMemorySize, eu1_smem);

    // ---- CSR build (once per launch; reused by both layers) ----
    zero_cnt_kernel<<<cdiv(NN, 256), 256>>>();
    hist_kernel<<<cdiv(EE, 256), 256>>>(e_dst);
    scan1_kernel<<<cdiv(NN, 1024), 1024>>>();
    scan2_kernel<<<1, 128>>>(cdiv(NN, 1024));
    scan3_kernel<<<cdiv(NN, 256), 256>>>();
    place_kernel<<<cdiv(EE, 256), 256>>>(e_src, e_dst);

    // ---- embeddings ----
    rowgemm<FFI, HH, 0, false><<<cdiv(NN, 128), 128>>>(x, node_w, node_b, p_h, nullptr, NN);
    // edge embed written directly in dst-sorted order (gather via perm)
    rowgemm<DDI, HH, 0, true><<<cdiv(EE, 128), 128>>>(edge_attr, edge_w, edge_b, p_ea, p_perm, EE);
    rowgemm<DDI, HH, 0, false><<<cdiv(ETT, 128), 128>>>(tea_in, edge_w, edge_b, p_tea, nullptr, ETT);

    // ---- layers ----
    for (int l = 0; l < LLY; l++) {
        aggregate_kernel<<<cdiv(NN, 8), 256>>>(p_h, p_ea, p_aggr);
        rowgemm<HH, HH, 1, false><<<cdiv(NN, 128), 128>>>(p_aggr, conv_w1 + l * HH * HH,
                                                          conv_b1 + l * HH, p_t, nullptr, NN);
        rowgemm<HH, HH, 0, false><<<cdiv(NN, 128), 128>>>(p_t, conv_w2 + l * HH * HH,
                                                          conv_b2 + l * HH, p_z, nullptr, NN);
        {
            dim3 bs(HH, 8);
            bnstats_kernel<<<264, bs>>>(p_z, NN);
        }
        bnfinal_kernel<<<1, HH>>>(NN);
        {
            dim3 bs(HH, 4);
            hup_kernel<<<cdiv(NN, 4), bs>>>(bn_gamma + l * HH, bn_beta + l * HH, NN);
        }
        eu1_kernel<<<cdiv(ETT, 128), 128, eu1_smem>>>(p_h, p_tea, tsrc, tdst,
                                                      emlp_w1 + l * 3 * HH * HH,
                                                      emlp_b1 + l * HH, p_ehid, ETT);
        rowgemm<HH, HH, 2, false><<<cdiv(ETT, 128), 128>>>(p_ehid, emlp_w2 + l * HH * HH,
                                                           emlp_b2 + l * HH, p_tea, nullptr, ETT);
    }

    // ---- final classifier ----
    f1_kernel<<<cdiv(ETT, 128), 128>>>(p_h, p_tea, tsrc, tdst, mlp_w1, mlp_b1, p_o1, ETT);
    f23_kernel<<<cdiv(ETT, 128), 128>>>(p_o1, mlp_w2, mlp_b2, mlp_w3, mlp_b3,
                                        (float*)d_out, ETT);
}

// round 3
// speedup vs baseline: 2.2636x; 1.0047x over previous
#include <cuda_runtime.h>
#include <cstdint>
#include <cstddef>

#define NN   100000
#define EE   1000000
#define ETT  200000
#define FFI  64
#define DDI  32
#define HH   66
#define HS   68          // padded row stride (16B aligned); pad cols always zero
#define LLY  2
#define BN_EPS 1e-5f

static inline int cdiv(int a, int b) { return (a + b - 1) / b; }

// ---------------- scratch (static device globals; zero-initialized) ----------------
__device__ float g_h   [(size_t)NN  * HS];
__device__ float g_ea  [(size_t)EE  * HS];   // embedded edge attrs, dst-sorted order
__device__ float g_tea [(size_t)ETT * HS];
__device__ float g_aggr[(size_t)NN  * HS];
__device__ float g_z   [(size_t)NN  * HS];
__device__ float g_sum[HH];
__device__ float g_sumsq[HH];
__device__ float g_mean[HH];
__device__ float g_invstd[HH];
// CSR scratch
__device__ int g_cnt[NN];
__device__ int g_rowstart[NN + 1];
__device__ int g_cursor[NN];
__device__ int g_bsum[128];
__device__ int g_boff[128];
__device__ int g_perm[EE];
__device__ int g_srcs[EE];

// ================= CSR build =================
__global__ void zero_cnt_kernel()
{
    int i = blockIdx.x * blockDim.x + threadIdx.x;
    if (i < NN) g_cnt[i] = 0;
}

__global__ void hist_kernel(const int* __restrict__ dst)
{
    int e = blockIdx.x * blockDim.x + threadIdx.x;
    if (e < EE) atomicAdd(&g_cnt[dst[e]], 1);
}

__global__ void scan1_kernel()
{
    __shared__ int sh[1024];
    int i = blockIdx.x * 1024 + threadIdx.x;
    int v = (i < NN) ? g_cnt[i] : 0;
    sh[threadIdx.x] = v;
    __syncthreads();
    for (int off = 1; off < 1024; off <<= 1) {
        int t = (threadIdx.x >= off) ? sh[threadIdx.x - off] : 0;
        __syncthreads();
        sh[threadIdx.x] += t;
        __syncthreads();
    }
    if (i < NN) g_rowstart[i] = sh[threadIdx.x] - v;
    if (threadIdx.x == 1023) g_bsum[blockIdx.x] = sh[1023];
}

__global__ void scan2_kernel(int nb)
{
    __shared__ int sh[128];
    int t = threadIdx.x;
    int v = (t < nb) ? g_bsum[t] : 0;
    sh[t] = v;
    __syncthreads();
    for (int off = 1; off < 128; off <<= 1) {
        int u = (t >= off) ? sh[t - off] : 0;
        __syncthreads();
        sh[t] += u;
        __syncthreads();
    }
    g_boff[t] = sh[t] - v;
}

__global__ void scan3_kernel()
{
    int i = blockIdx.x * blockDim.x + threadIdx.x;
    if (i < NN) {
        int rs = g_rowstart[i] + g_boff[i >> 10];
        g_rowstart[i] = rs;
        g_cursor[i] = rs;
    }
    if (i == 0) g_rowstart[NN] = EE;
}

__global__ void place_kernel(const int* __restrict__ src, const int* __restrict__ dst)
{
    int e = blockIdx.x * blockDim.x + threadIdx.x;
    if (e >= EE) return;
    int d = dst[e];
    int pos = atomicAdd(&g_cursor[d], 1);
    g_perm[pos] = e;
    g_srcs[pos] = src[e];
}

// ================= generic tall-skinny row GEMM (embeddings) =================
template <int K, int HOUT, bool GATHER>
__global__ void __launch_bounds__(256)
rowgemm(const float* __restrict__ A, const float* __restrict__ W,
        const float* __restrict__ bias, float* __restrict__ out,
        const int* __restrict__ perm, int M)
{
    constexpr int KP = (K + 3) & ~3;
    constexpr int HP = (HOUT + 3) & ~3;
    __shared__ float sW[KP * HP];
    __shared__ float sb[HP];
    for (int i = threadIdx.x; i < KP * HP; i += blockDim.x) {
        int k = i / HP, j = i % HP;
        sW[i] = (k < K && j < HOUT) ? W[k * HOUT + j] : 0.0f;
    }
    for (int i = threadIdx.x; i < HP; i += blockDim.x)
        sb[i] = (i < HOUT) ? bias[i] : 0.0f;
    __syncthreads();

    int r = blockIdx.x * blockDim.x + threadIdx.x;
    if (r >= M) return;
    int ra = GATHER ? perm[r] : r;

    float acc[HP];
#pragma unroll
    for (int j = 0; j < HP; j++) acc[j] = sb[j];

    const float4* a4 = reinterpret_cast<const float4*>(A + (size_t)ra * KP);
#pragma unroll 2
    for (int kk = 0; kk < KP / 4; kk++) {
        float4 av = __ldg(&a4[kk]);
#pragma unroll
        for (int s = 0; s < 4; s++) {
            float a = (s == 0) ? av.x : (s == 1) ? av.y : (s == 2) ? av.z : av.w;
            const float4* w4 = reinterpret_cast<const float4*>(&sW[(kk * 4 + s) * HP]);
#pragma unroll
            for (int j = 0; j < HP / 4; j++) {
                float4 w = w4[j];
                acc[4 * j + 0] = fmaf(a, w.x, acc[4 * j + 0]);
                acc[4 * j + 1] = fmaf(a, w.y, acc[4 * j + 1]);
                acc[4 * j + 2] = fmaf(a, w.z, acc[4 * j + 2]);
                acc[4 * j + 3] = fmaf(a, w.w, acc[4 * j + 3]);
            }
        }
    }

    float4* o4 = reinterpret_cast<float4*>(out + (size_t)r * HP);
#pragma unroll
    for (int j = 0; j < HP / 4; j++) {
        float4 v;
        v.x = acc[4 * j + 0]; v.y = acc[4 * j + 1];
        v.z = acc[4 * j + 2]; v.w = acc[4 * j + 3];
        o4[j] = v;
    }
}

// ================= aggregation =================
__global__ void aggregate_kernel(const float* __restrict__ h, const float* __restrict__ ea,
                                 float* __restrict__ aggr)
{
    int warp = (blockIdx.x * blockDim.x + threadIdx.x) >> 5;
    int lane = threadIdx.x & 31;
    if (warp >= NN) return;
    int beg = g_rowstart[warp];
    int end = g_rowstart[warp + 1];
    bool has2 = lane < 2;
    int c2 = lane + 64;
    float a0 = 0.f, a1 = 0.f, a2 = 0.f;
    for (int p = beg; p < end; p++) {
        int s = g_srcs[p];
        const float* er = ea + (size_t)p * HS;
        const float* hr = h + (size_t)s * HS;
        a0 += fmaxf(hr[lane]      + er[lane],      0.f);
        a1 += fmaxf(hr[lane + 32] + er[lane + 32], 0.f);
        if (has2) a2 += fmaxf(hr[c2] + er[c2], 0.f);
    }
    const float* hd = h + (size_t)warp * HS;
    float* o = aggr + (size_t)warp * HS;
    o[lane]      = hd[lane]      + a0;
    o[lane + 32] = hd[lane + 32] + a1;
    if (has2) o[c2] = hd[c2] + a2;
}

// ================= conv MLP fused: z = relu(aggr@W1+b1)@W2 + b2 =================
__global__ void __launch_bounds__(128)
conv_fused(const float* __restrict__ A,
           const float* __restrict__ W1, const float* __restrict__ b1,
           const float* __restrict__ W2, const float* __restrict__ b2,
           float* __restrict__ z, int M)
{
    __shared__ float sW1[HS * HS];
    __shared__ float sW2[HS * HS];
    __shared__ float sb1[HS], sb2[HS];
    for (int i = threadIdx.x; i < HS * HS; i += blockDim.x) {
        int k = i / HS, j = i % HS;
        bool ok = (k < HH && j < HH);
        sW1[i] = ok ? W1[k * HH + j] : 0.0f;
        sW2[i] = ok ? W2[k * HH + j] : 0.0f;
    }
    for (int i = threadIdx.x; i < HS; i += blockDim.x) {
        sb1[i] = (i < HH) ? b1[i] : 0.0f;
        sb2[i] = (i < HH) ? b2[i] : 0.0f;
    }
    __syncthreads();

    int r = blockIdx.x * blockDim.x + threadIdx.x;
    if (r >= M) return;

    float hid[HS];
#pragma unroll
    for (int j = 0; j < HS; j++) hid[j] = sb1[j];

    const float4* a4 = reinterpret_cast<const float4*>(A + (size_t)r * HS);
#pragma unroll 2
    for (int kk = 0; kk < HS / 4; kk++) {
        float4 av = __ldg(&a4[kk]);
#pragma unroll
        for (int s = 0; s < 4; s++) {
            float a = (s == 0) ? av.x : (s == 1) ? av.y : (s == 2) ? av.z : av.w;
            const float4* w4 = reinterpret_cast<const float4*>(&sW1[(kk * 4 + s) * HS]);
#pragma unroll
            for (int j = 0; j < HS / 4; j++) {
                float4 w = w4[j];
                hid[4 * j + 0] = fmaf(a, w.x, hid[4 * j + 0]);
                hid[4 * j + 1] = fmaf(a, w.y, hid[4 * j + 1]);
                hid[4 * j + 2] = fmaf(a, w.z, hid[4 * j + 2]);
                hid[4 * j + 3] = fmaf(a, w.w, hid[4 * j + 3]);
            }
        }
    }
#pragma unroll
    for (int j = 0; j < HS; j++) hid[j] = fmaxf(hid[j], 0.0f);

    float acc[HS];
#pragma unroll
    for (int j = 0; j < HS; j++) acc[j] = sb2[j];
#pragma unroll
    for (int k = 0; k < HS; k++) {
        float a = hid[k];
        const float4* w4 = reinterpret_cast<const float4*>(&sW2[k * HS]);
#pragma unroll
        for (int j = 0; j < HS / 4; j++) {
            float4 w = w4[j];
            acc[4 * j + 0] = fmaf(a, w.x, acc[4 * j + 0]);
            acc[4 * j + 1] = fmaf(a, w.y, acc[4 * j + 1]);
            acc[4 * j + 2] = fmaf(a, w.z, acc[4 * j + 2]);
            acc[4 * j + 3] = fmaf(a, w.w, acc[4 * j + 3]);
        }
    }

    float4* o4 = reinterpret_cast<float4*>(z + (size_t)r * HS);
#pragma unroll
    for (int j = 0; j < HS / 4; j++) {
        float4 v;
        v.x = acc[4 * j + 0]; v.y = acc[4 * j + 1];
        v.z = acc[4 * j + 2]; v.w = acc[4 * j + 3];
        o4[j] = v;
    }
}

// ================= BN stats / final / h update =================
__global__ void bnstats_kernel(const float* __restrict__ z, int M)
{
    __shared__ float ssum[8][HH + 2];
    __shared__ float ssq [8][HH + 2];
    int c  = threadIdx.x;
    int ty = threadIdx.y;
    float s = 0.f, q = 0.f;
    for (int r = blockIdx.x * 8 + ty; r < M; r += gridDim.x * 8) {
        float v = z[(size_t)r * HS + c];
        s += v; q += v * v;
    }
    ssum[ty][c] = s; ssq[ty][c] = q;
    __syncthreads();
    for (int off = 4; off >= 1; off >>= 1) {
        if (ty < off) { ssum[ty][c] += ssum[ty + off][c]; ssq[ty][c] += ssq[ty + off][c]; }
        __syncthreads();
    }
    if (ty == 0) {
        atomicAdd(&g_sum[c],   ssum[0][c]);
        atomicAdd(&g_sumsq[c], ssq[0][c]);
    }
}

__global__ void bnfinal_kernel(int n)
{
    int c = threadIdx.x;
    if (c < HH) {
        float m = g_sum[c] / (float)n;
        float v = g_sumsq[c] / (float)n - m * m;
        g_mean[c] = m;
        g_invstd[c] = rsqrtf(v + BN_EPS);
        g_sum[c] = 0.0f;
        g_sumsq[c] = 0.0f;
    }
}

__global__ void hup_kernel(const float* __restrict__ gamma, const float* __restrict__ beta, int M)
{
    int c = threadIdx.x;
    int r = blockIdx.x * blockDim.y + threadIdx.y;
    if (r >= M) return;
    size_t i = (size_t)r * HS + c;
    float bn = (g_z[i] - g_mean[c]) * g_invstd[c] * gamma[c] + beta[c];
    g_h[i] = 0.5f * (g_h[i] + fmaxf(bn, 0.0f));
}

// ================= edge-update fused: tea += 0.5*(relu(cat@W1+b1)@W2 + b2) =========
__global__ void __launch_bounds__(128)
eu_fused(const float* __restrict__ h, float* __restrict__ tea,
         const int* __restrict__ tsrc, const int* __restrict__ tdst,
         const float* __restrict__ W1, const float* __restrict__ b1,
         const float* __restrict__ W2, const float* __restrict__ b2, int M)
{
    extern __shared__ float dsm[];
    float* sW1 = dsm;                        // [204][68]
    float* sW2 = dsm + 204 * HS;             // [68][68]
    float* sb1 = sW2 + HS * HS;              // [68]
    float* sb2 = sb1 + HS;                   // [68]
    for (int i = threadIdx.x; i < 204 * HS; i += blockDim.x) sW1[i] = 0.0f;
    for (int i = threadIdx.x; i < HS * HS; i += blockDim.x) {
        int k = i / HS, j = i % HS;
        sW2[i] = (k < HH && j < HH) ? W2[k * HH + j] : 0.0f;
    }
    for (int i = threadIdx.x; i < HS; i += blockDim.x) {
        sb1[i] = (i < HH) ? b1[i] : 0.0f;
        sb2[i] = (i < HH) ? b2[i] : 0.0f;
    }
    __syncthreads();
    for (int i = threadIdx.x; i < 3 * HH * HH; i += blockDim.x) {
        int k = i / HH, j = i % HH;
        int seg = k / HH, kk = k % HH;
        sW1[(seg * HS + kk) * HS + j] = W1[k * HH + j];
    }
    __syncthreads();

    int r = blockIdx.x * blockDim.x + threadIdx.x;
    if (r >= M) return;

    float hid[HS];
#pragma unroll
    for (int j = 0; j < HS; j++) hid[j] = sb1[j];

    int si = tsrc[r], di = tdst[r];
    const float* bases[3] = { h + (size_t)si * HS, h + (size_t)di * HS, tea + (size_t)r * HS };

#pragma unroll 1
    for (int seg = 0; seg < 3; seg++) {
        const float4* a4 = reinterpret_cast<const float4*>(bases[seg]);
#pragma unroll 2
        for (int kk = 0; kk < HS / 4; kk++) {
            float4 av = __ldg(&a4[kk]);
#pragma unroll
            for (int s = 0; s < 4; s++) {
                float a = (s == 0) ? av.x : (s == 1) ? av.y : (s == 2) ? av.z : av.w;
                const float4* w4 = reinterpret_cast<const float4*>(&sW1[(seg * HS + kk * 4 + s) * HS]);
#pragma unroll
                for (int j = 0; j < HS / 4; j++) {
                    float4 w = w4[j];
                    hid[4 * j + 0] = fmaf(a, w.x, hid[4 * j + 0]);
                    hid[4 * j + 1] = fmaf(a, w.y, hid[4 * j + 1]);
                    hid[4 * j + 2] = fmaf(a, w.z, hid[4 * j + 2]);
                    hid[4 * j + 3] = fmaf(a, w.w, hid[4 * j + 3]);
                }
            }
        }
    }
#pragma unroll
    for (int j = 0; j < HS; j++) hid[j] = fmaxf(hid[j], 0.0f);

    float acc[HS];
#pragma unroll
    for (int j = 0; j < HS; j++) acc[j] = sb2[j];
#pragma unroll
    for (int k = 0; k < HS; k++) {
        float a = hid[k];
        const float4* w4 = reinterpret_cast<const float4*>(&sW2[k * HS]);
#pragma unroll
        for (int j = 0; j < HS / 4; j++) {
            float4 w = w4[j];
            acc[4 * j + 0] = fmaf(a, w.x, acc[4 * j + 0]);
            acc[4 * j + 1] = fmaf(a, w.y, acc[4 * j + 1]);
            acc[4 * j + 2] = fmaf(a, w.z, acc[4 * j + 2]);
            acc[4 * j + 3] = fmaf(a, w.w, acc[4 * j + 3]);
        }
    }

    float4* t4 = reinterpret_cast<float4*>(tea + (size_t)r * HS);
#pragma unroll
    for (int j = 0; j < HS / 4; j++) {
        float4 ov = t4[j];
        float4 v;
        v.x = ov.x + 0.5f * acc[4 * j + 0];
        v.y = ov.y + 0.5f * acc[4 * j + 1];
        v.z = ov.z + 0.5f * acc[4 * j + 2];
        v.w = ov.w + 0.5f * acc[4 * j + 3];
        t4[j] = v;
    }
}

// ================= final MLP fused (3 layers) =================
__global__ void __launch_bounds__(128)
f_fused(const float* __restrict__ h, const float* __restrict__ tea,
        const int* __restrict__ tsrc, const int* __restrict__ tdst,
        const float* __restrict__ W1, const float* __restrict__ b1,
        const float* __restrict__ W2, const float* __restrict__ b2,
        const float* __restrict__ W3, const float* __restrict__ b3,
        float* __restrict__ out, int M)
{
    extern __shared__ float dsm[];
    float* sW1 = dsm;                 // [204][52]
    float* sW2 = sW1 + 204 * 52;      // [52][28]
    float* sW3 = sW2 + 52 * 28;       // [25][4]
    float* sb1 = sW3 + 25 * 4;        // [52]
    float* sb2 = sb1 + 52;            // [28]
    float* sb3 = sb2 + 28;            // [2]
    for (int i = threadIdx.x; i < 204 * 52; i += blockDim.x) sW1[i] = 0.0f;
    for (int i = threadIdx.x; i < 52 * 28; i += blockDim.x) {
        int k = i / 28, j = i % 28;
        sW2[i] = (k < 50 && j < 25) ? W2[k * 25 + j] : 0.0f;
    }
    for (int i = threadIdx.x; i < 25 * 4; i += blockDim.x) {
        int k = i / 4, j = i % 4;
        sW3[i] = (j < 2) ? W3[k * 2 + j] : 0.0f;
    }
    for (int i = threadIdx.x; i < 52; i += blockDim.x) sb1[i] = (i < 50) ? b1[i] : 0.0f;
    for (int i = threadIdx.x; i < 28; i += blockDim.x) sb2[i] = (i < 25) ? b2[i] : 0.0f;
    if (threadIdx.x < 2) sb3[threadIdx.x] = b3[threadIdx.x];
    __syncthreads();
    for (int i = threadIdx.x; i < 3 * HH * 50; i += blockDim.x) {
        int k = i / 50, j = i % 50;
        int seg = k / HH, kk = k % HH;
        sW1[(seg * HS + kk) * 52 + j] = W1[k * 50 + j];
    }
    __syncthreads();

    int r = blockIdx.x * blockDim.x + threadIdx.x;
    if (r >= M) return;

    float hid[52];
#pragma unroll
    for (int j = 0; j < 52; j++) hid[j] = sb1[j];

    int si = tsrc[r], di = tdst[r];
    const float* bases[3] = { h + (size_t)si * HS, h + (size_t)di * HS, tea + (size_t)r * HS };

#pragma unroll 1
    for (int seg = 0; seg < 3; seg++) {
        bool rl = (seg < 2);
        const float4* a4 = reinterpret_cast<const float4*>(bases[seg]);
#pragma unroll 2
        for (int kk = 0; kk < HS / 4; kk++) {
            float4 av = __ldg(&a4[kk]);
            if (rl) {
                av.x = fmaxf(av.x, 0.f); av.y = fmaxf(av.y, 0.f);
                av.z = fmaxf(av.z, 0.f); av.w = fmaxf(av.w, 0.f);
            }
#pragma unroll
            for (int s = 0; s < 4; s++) {
                float a = (s == 0) ? av.x : (s == 1) ? av.y : (s == 2) ? av.z : av.w;
                const float4* w4 = reinterpret_cast<const float4*>(&sW1[(seg * HS + kk * 4 + s) * 52]);
#pragma unroll
                for (int j = 0; j < 13; j++) {
                    float4 w = w4[j];
                    hid[4 * j + 0] = fmaf(a, w.x, hid[4 * j + 0]);
                    hid[4 * j + 1] = fmaf(a, w.y, hid[4 * j + 1]);
                    hid[4 * j + 2] = fmaf(a, w.z, hid[4 * j + 2]);
                    hid[4 * j + 3] = fmaf(a, w.w, hid[4 * j + 3]);
                }
            }
        }
    }
#pragma unroll
    for (int j = 0; j < 52; j++) hid[j] = fmaxf(hid[j], 0.0f);

    float acc[28];
#pragma unroll
    for (int j = 0; j < 28; j++) acc[j] = sb2[j];
#pragma unroll
    for (int k = 0; k < 52; k++) {
        float a = hid[k];
        const float4* w4 = reinterpret_cast<const float4*>(&sW2[k * 28]);
#pragma unroll
        for (int j = 0; j < 7; j++) {
            float4 w = w4[j];
            acc[4 * j + 0] = fmaf(a, w.x, acc[4 * j + 0]);
            acc[4 * j + 1] = fmaf(a, w.y, acc[4 * j + 1]);
            acc[4 * j + 2] = fmaf(a, w.z, acc[4 * j + 2]);
            acc[4 * j + 3] = fmaf(a, w.w, acc[4 * j + 3]);
        }
    }

    float o0 = sb3[0], o1v = sb3[1];
#pragma unroll
    for (int k = 0; k < 25; k++) {
        float a = fmaxf(acc[k], 0.f);
        o0  = fmaf(a, sW3[k * 4 + 0], o0);
        o1v = fmaf(a, sW3[k * 4 + 1], o1v);
    }
    out[(size_t)r * 2 + 0] = o0;
    out[(size_t)r * 2 + 1] = o1v;
}

// =======================================================================================
extern "C" void kernel_launch(void* const* d_in, const int* in_sizes, int n_in,
                              void* d_out, int out_size)
{
    const float *x, *edge_attr, *tea_in, *node_w, *node_b, *edge_w, *edge_b;
    const float *conv_w1, *conv_b1, *conv_w2, *conv_b2, *bn_gamma, *bn_beta;
    const float *emlp_w1, *emlp_b1, *emlp_w2, *emlp_b2;
    const float *mlp_w1, *mlp_b1, *mlp_w2, *mlp_b2, *mlp_w3, *mlp_b3;
    const int *edge_index, *eli;

    if (in_sizes[1] == 2 * EE) {
        x          = (const float*)d_in[0];
        edge_index = (const int*)  d_in[1];
        edge_attr  = (const float*)d_in[2];
        eli        = (const int*)  d_in[3];
        tea_in     = (const float*)d_in[4];
        node_w = (const float*)d_in[5];  node_b = (const float*)d_in[6];
        edge_w = (const float*)d_in[7];  edge_b = (const float*)d_in[8];
        conv_w1 = (const float*)d_in[9];  conv_b1 = (const float*)d_in[10];
        conv_w2 = (const float*)d_in[11]; conv_b2 = (const float*)d_in[12];
        bn_gamma = (const float*)d_in[13]; bn_beta = (const float*)d_in[14];
        emlp_w1 = (const float*)d_in[15]; emlp_b1 = (const float*)d_in[16];
        emlp_w2 = (const float*)d_in[17]; emlp_b2 = (const float*)d_in[18];
        mlp_w1 = (const float*)d_in[19]; mlp_b1 = (const float*)d_in[20];
        mlp_w2 = (const float*)d_in[21]; mlp_b2 = (const float*)d_in[22];
        mlp_w3 = (const float*)d_in[23]; mlp_b3 = (const float*)d_in[24];
    } else {
        x         = (const float*)d_in[0];
        edge_attr = (const float*)d_in[1];
        tea_in    = (const float*)d_in[2];
        node_w = (const float*)d_in[3];  node_b = (const float*)d_in[4];
        edge_w = (const float*)d_in[5];  edge_b = (const float*)d_in[6];
        conv_w1 = (const float*)d_in[7];  conv_b1 = (const float*)d_in[8];
        conv_w2 = (const float*)d_in[9];  conv_b2 = (const float*)d_in[10];
        bn_gamma = (const float*)d_in[11]; bn_beta = (const float*)d_in[12];
        emlp_w1 = (const float*)d_in[13]; emlp_b1 = (const float*)d_in[14];
        emlp_w2 = (const float*)d_in[15]; emlp_b2 = (const float*)d_in[16];
        mlp_w1 = (const float*)d_in[17]; mlp_b1 = (const float*)d_in[18];
        mlp_w2 = (const float*)d_in[19]; mlp_b2 = (const float*)d_in[20];
        mlp_w3 = (const float*)d_in[21]; mlp_b3 = (const float*)d_in[22];
        edge_index = (const int*)d_in[23];
        eli        = (const int*)d_in[24];
    }

    const int* e_src = edge_index;
    const int* e_dst = edge_index + EE;
    const int* tsrc  = eli;
    const int* tdst  = eli + ETT;

    float *p_h, *p_ea, *p_tea, *p_aggr, *p_z;
    int *p_perm;
    cudaGetSymbolAddress((void**)&p_h,    g_h);
    cudaGetSymbolAddress((void**)&p_ea,   g_ea);
    cudaGetSymbolAddress((void**)&p_tea,  g_tea);
    cudaGetSymbolAddress((void**)&p_aggr, g_aggr);
    cudaGetSymbolAddress((void**)&p_z,    g_z);
    cudaGetSymbolAddress((void**)&p_perm, g_perm);

    const int eu_smem = (204 * HS + HS * HS + 2 * HS) * 4;
    cudaFuncSetAttribute(eu_fused, cudaFuncAttributeMaxDynamicSharedMemorySize, eu_smem);
    const int f_smem = (204 * 52 + 52 * 28 + 25 * 4 + 52 + 28 + 2) * 4;
    cudaFuncSetAttribute(f_fused, cudaFuncAttributeMaxDynamicSharedMemorySize, f_smem);

    // ---- CSR build ----
    zero_cnt_kernel<<<cdiv(NN, 256), 256>>>();
    hist_kernel<<<cdiv(EE, 256), 256>>>(e_dst);
    scan1_kernel<<<cdiv(NN, 1024), 1024>>>();
    scan2_kernel<<<1, 128>>>(cdiv(NN, 1024));
    scan3_kernel<<<cdiv(NN, 256), 256>>>();
    place_kernel<<<cdiv(EE, 256), 256>>>(e_src, e_dst);

    // ---- embeddings ----
    rowgemm<FFI, HH, false><<<cdiv(NN, 256), 256>>>(x, node_w, node_b, p_h, nullptr, NN);
    rowgemm<DDI, HH, true><<<cdiv(EE, 256), 256>>>(edge_attr, edge_w, edge_b, p_ea, p_perm, EE);
    rowgemm<DDI, HH, false><<<cdiv(ETT, 256), 256>>>(tea_in, edge_w, edge_b, p_tea, nullptr, ETT);

    // ---- layers ----
    for (int l = 0; l < LLY; l++) {
        aggregate_kernel<<<cdiv(NN, 8), 256>>>(p_h, p_ea, p_aggr);
        conv_fused<<<cdiv(NN, 128), 128>>>(p_aggr,
                                           conv_w1 + l * HH * HH, conv_b1 + l * HH,
                                           conv_w2 + l * HH * HH, conv_b2 + l * HH,
                                           p_z, NN);
        {
            dim3 bs(HH, 8);
            bnstats_kernel<<<264, bs>>>(p_z, NN);
        }
        bnfinal_kernel<<<1, HH>>>(NN);
        {
            dim3 bs(HH, 4);
            hup_kernel<<<cdiv(NN, 4), bs>>>(bn_gamma + l * HH, bn_beta + l * HH, NN);
        }
        eu_fused<<<cdiv(ETT, 128), 128, eu_smem>>>(p_h, p_tea, tsrc, tdst,
                                                   emlp_w1 + l * 3 * HH * HH, emlp_b1 + l * HH,
                                                   emlp_w2 + l * HH * HH, emlp_b2 + l * HH, ETT);
    }

    // ---- final classifier ----
    f_fused<<<cdiv(ETT, 128), 128, f_smem>>>(p_h, p_tea, tsrc, tdst,
                                             mlp_w1, mlp_b1, mlp_w2, mlp_b2,
                                             mlp_w3, mlp_b3, (float*)d_out, ETT);
}